// round 5
// baseline (speedup 1.0000x reference)
#include <cuda_runtime.h>

// LIF scan, single-pass, minimal-latency chain.
// B=16, S=256, H=128, N=64. T = S*H = 32768 sequential steps per (b,n) chain.
//
// Chain (carried value = post-add accumulator v; bit-identical to reference):
//     t  = v + x'            FADD   (dep v)
//     p  = (v <= thr)        FSETP  (dep v, parallel with FADD)
//     v' = p ? t : x'        FSEL   (pred-as-data; fl(0+x') == x' exact)
//     out_prev = p ? 0 : v   FSEL   (off-chain, reuses p; out of PREVIOUS step)
// Critical path ~8 cyc/step.
//
// The staged out stream is therefore shifted by one step: staged element j of
// row r is the out of global step r*128 + j - 1. The flusher un-shifts it;
// the producer writes the final step's out directly; row 0 element 0 (the
// phantom "out of acc0") is skipped.
//
// Warps per CTA (32 CTAs = batch x neuron-half, 96 threads):
//   warp0 producer (chain + smem staging), warp1 flusher (coalesced STG of
//   outs + synthesized spikes), warp2 x-loader (one s-row ahead, smem ring).

#define BB 16
#define SS 256
#define HH 128
#define NN 64
#define TT (SS * HH)
#define ROWPAD 132

static const size_t BSNH = (size_t)BB * SS * NN * HH;

__global__ void __launch_bounds__(96, 1)
lif_fused(const float* __restrict__ x,
          const float* __restrict__ thresh,
          const float* __restrict__ acc0,
          float* __restrict__ outbuf,
          int write_spikes)
{
    __shared__ float sbuf[2][32 * ROWPAD];
    __shared__ float xsh[2][ROWPAD];

    const int tid  = threadIdx.x;
    const int wid  = tid >> 5;
    const int lane = tid & 31;
    const int b    = blockIdx.x >> 1;
    const int n0   = (blockIdx.x & 1) * 32;

    const float* __restrict__ xg = x + (size_t)b * TT;

    if (wid == 2) {                          // preload x row 0
        ((float4*)xsh[0])[lane] = ((const float4*)xg)[lane];
    }
    __syncthreads();

    if (wid == 0) {
        // ---------------- producer ----------------
        const int n = n0 + lane;
        const float thr = thresh[n];
        float v = acc0[b * NN + n];

        float* const myrow0 = &sbuf[0][lane * ROWPAD];
        float* const myrow1 = &sbuf[1][lane * ROWPAD];

        for (int r = 0; r < SS; ++r) {
            const float4* xrow = (const float4*)xsh[r & 1];
            float* rw = (r & 1) ? myrow1 : myrow0;

            float4 xv = xrow[0];
            #pragma unroll 8
            for (int q = 0; q < HH / 4; ++q) {
                float4 xn = xrow[q + 1];     // ring/pad overread is harmless
                float4 o;
                { float t = v + xv.x; bool p = (v <= thr);
                  o.x = p ? 0.0f : v;  v = p ? t : xv.x; }
                { float t = v + xv.y; bool p = (v <= thr);
                  o.y = p ? 0.0f : v;  v = p ? t : xv.y; }
                { float t = v + xv.z; bool p = (v <= thr);
                  o.z = p ? 0.0f : v;  v = p ? t : xv.z; }
                { float t = v + xv.w; bool p = (v <= thr);
                  o.w = p ? 0.0f : v;  v = p ? t : xv.w; }
                *(float4*)&rw[q * 4] = o;
                xv = xn;
            }
            __syncthreads();
        }
        // final step's out (never staged due to the one-step shift)
        {
            float lastout = (v <= thr) ? 0.0f : v;
            size_t pos = (((size_t)b * SS + (SS - 1)) * NN + n) * HH + (HH - 1);
            outbuf[pos] = lastout;
            if (write_spikes)
                outbuf[BSNH + pos] = (lastout > 0.0f) ? 1.0f : 0.0f;
        }
    } else if (wid == 2) {
        // ---------------- x loader ----------------
        for (int r = 0; r < SS; ++r) {
            if (r + 1 < SS)
                ((float4*)xsh[(r + 1) & 1])[lane] =
                    ((const float4*)(xg + (size_t)(r + 1) * HH))[lane];
            __syncthreads();
        }
    } else {
        // ---------------- flusher ----------------
        float* __restrict__ outp = outbuf;
        float* __restrict__ spkp = outbuf + BSNH;

        for (int r = 0; r < SS; ++r) {
            __syncthreads();
            const float* buf = sbuf[r & 1];
            const int s = r;
            size_t rowbase = (((size_t)b * SS + s) * NN + n0) * HH;

            // boundary elements: staged[rr][0] -> (s-1, n0+rr, HH-1)
            if (s > 0 && lane == 0) {
                for (int rr = 0; rr < 32; ++rr) {
                    float bv = buf[rr * ROWPAD];
                    size_t pp = rowbase + (size_t)rr * HH
                              - (size_t)NN * HH + (HH - 1);
                    outp[pp] = bv;
                    if (write_spikes) spkp[pp] = (bv > 0.0f) ? 1.0f : 0.0f;
                }
            }
            // body: staged[rr][1..127] -> (s, n0+rr, 0..126), coalesced
            #pragma unroll 2
            for (int rr = 0; rr < 32; ++rr) {
                const float* src = &buf[rr * ROWPAD];
                size_t nb = rowbase + (size_t)rr * HH;
                for (int h = lane; h < HH - 1; h += 32) {
                    float vv = src[h + 1];
                    outp[nb + h] = vv;
                    if (write_spikes) spkp[nb + h] = (vv > 0.0f) ? 1.0f : 0.0f;
                }
            }
        }
    }
}

extern "C" void kernel_launch(void* const* d_in, const int* in_sizes, int n_in,
                              void* d_out, int out_size)
{
    const float* x      = (const float*)d_in[0];
    const float* thresh = (const float*)d_in[1];
    const float* acc0   = (const float*)d_in[2];
    float* out = (float*)d_out;

    int write_spikes = ((size_t)out_size >= 2 * BSNH) ? 1 : 0;

    lif_fused<<<32, 96>>>(x, thresh, acc0, out, write_spikes);
}

// round 6
// speedup vs baseline: 4.6762x; 4.6762x over previous
#include <cuda_runtime.h>

// LIF scan, exact two-phase checkpointing, v2.
// B=16, S=256, H=128, N=64.  T = S*H = 32768 steps per (b,n) chain.
//
// Phase 1 (lif_prepass): serial state-only chain. Two warps per CTA:
//   warp0 runs the recurrence reading x from smem (broadcast LDS, fully
//   latency-covered), warp1 prefetches x in 8-row double-buffered blocks.
//   Records the TRUE carried state every 8 s-rows (32 checkpoints/chain).
// Phase 2 (lif_output): 1024 independent CTAs replay one 8-row block each
//   from its exact checkpoint; smem-transpose producer/flusher pair gives
//   fully coalesced 512B stores of outs + synthesized spikes.
//
// Step math (bit-identical to the reference sequential order, all
// fixed-latency ops, no predicates on the carried chain):
//   m = (v <= thr) ? 1.0f : 0.0f     (FSET; reset folded into the FFMA)
//   v = fmaf(v, m, x)                (v*1+x == round(v+x); v*0+x == x)
//   g = (v > thr) ? 1.0f : 0.0f      (off-chain; g IS the spike value)
//   out = v * g                      (exactly v when fired, else 0)

#define BB 16
#define SS 256
#define HH 128
#define NN 64
#define TT (SS * HH)

#define BLKROWS 8              // s-rows per block (1024 steps)
#define NBLK (SS / BLKROWS)    // 32 checkpoints per chain
#define ROWPAD 132             // conflict-free float4 staging stride

static const size_t BSNH = (size_t)BB * SS * NN * HH;  // 33,554,432

// True chain states at block boundaries (raw carried v).
__device__ float g_chk[NBLK][BB][NN];

__device__ __forceinline__ float set_le(float a, float b) {
    float r; asm("set.le.f32.f32 %0, %1, %2;" : "=f"(r) : "f"(a), "f"(b)); return r;
}
__device__ __forceinline__ float set_gt(float a, float b) {
    float r; asm("set.gt.f32.f32 %0, %1, %2;" : "=f"(r) : "f"(a), "f"(b)); return r;
}

#define CHAIN_STEP(XC) do {                 \
    float _m = set_le(v, thr);              \
    v = __fmaf_rn(v, _m, (XC));             \
} while (0)

#define OUT_STEP(XC, OC) do {               \
    float _m = set_le(v, thr);              \
    v = __fmaf_rn(v, _m, (XC));             \
    float _g = set_gt(v, thr);              \
    (OC) = v * _g;                          \
} while (0)

// ---------------------------------------------------------------------------
// Phase 1: serial state chain with dedicated x-prefetch warp.
// grid = 32 (b, neuron-half), block = 64.
// ---------------------------------------------------------------------------
__global__ void __launch_bounds__(64, 1)
lif_prepass(const float* __restrict__ x,       // [B, S, H]
            const float* __restrict__ thresh,  // [N]
            const float* __restrict__ acc0)    // [B, N]
{
    // Two 8-row x blocks (4KB each) + one float4 of overread pad.
    __shared__ float xsh[2][BLKROWS * HH + 4];

    const int tid  = threadIdx.x;
    const int wid  = tid >> 5;
    const int lane = tid & 31;
    const int b    = blockIdx.x >> 1;
    const int half = blockIdx.x & 1;

    const float4* __restrict__ xg = (const float4*)(x + (size_t)b * TT);
    const int CHUNKS = BLKROWS * (HH / 4);   // 256 float4 per block

    // Preload block 0.
    if (wid == 1) {
        #pragma unroll
        for (int i = lane; i < CHUNKS; i += 32)
            ((float4*)xsh[0])[i] = xg[i];
    }
    __syncthreads();

    if (wid == 0) {
        // -------- chain warp: 32 neurons of (b, half) --------
        const int n = half * 32 + lane;
        const float thr = thresh[n];
        float v = acc0[b * NN + n];

        for (int blk = 0; blk < NBLK; ++blk) {
            g_chk[blk][b][n] = v;            // true state entering this block

            const float4* xs4 = (const float4*)xsh[blk & 1];
            float4 xv = xs4[0];
            #pragma unroll 8
            for (int q = 0; q < CHUNKS; ++q) {
                float4 xn = xs4[q + 1];      // broadcast LDS, pad-covered
                CHAIN_STEP(xv.x); CHAIN_STEP(xv.y);
                CHAIN_STEP(xv.z); CHAIN_STEP(xv.w);
                xv = xn;
            }
            __syncthreads();                 // block blk consumed; blk+1 ready
        }
    } else {
        // -------- loader warp: one block ahead --------
        for (int blk = 0; blk < NBLK; ++blk) {
            if (blk + 1 < NBLK) {
                const float4* src = xg + (size_t)(blk + 1) * CHUNKS;
                float4* dst = (float4*)xsh[(blk + 1) & 1];
                #pragma unroll
                for (int i = lane; i < CHUNKS; i += 32)
                    dst[i] = src[i];
            }
            __syncthreads();
        }
    }
}

// ---------------------------------------------------------------------------
// Phase 2: parallel block replay with coalesced output (unchanged from R4,
// measured 61us / 43% DRAM).
// grid = B * 2 * NBLK = 1024, block = 64 (warp0 producer, warp1 flusher).
// ---------------------------------------------------------------------------
__global__ void __launch_bounds__(64, 1)
lif_output(const float* __restrict__ x,
           const float* __restrict__ thresh,
           float* __restrict__ outbuf,
           int write_spikes)
{
    __shared__ float sbuf[2][32 * ROWPAD];

    const int tid  = threadIdx.x;
    const int sblk = blockIdx.x & (NBLK - 1);        // which s-block
    const int half = (blockIdx.x >> 5) & 1;          // neuron half
    const int b    = blockIdx.x >> 6;                // batch
    const int n0   = half * 32;
    const int s0   = sblk * BLKROWS;

    if (tid < 32) {
        // ---------------- producer: exact replay from checkpoint ---------
        const int lane = tid;
        const int n    = n0 + lane;
        const float thr = thresh[n];
        float v = g_chk[sblk][b][n];

        const float4* __restrict__ xp =
            (const float4*)(x + (size_t)b * TT + (size_t)s0 * HH);

        float* const row0 = &sbuf[0][lane * ROWPAD];
        float* const row1 = &sbuf[1][lane * ROWPAD];

        for (int r = 0; r < BLKROWS; ++r) {
            float* rw = (r & 1) ? row1 : row0;
            const float4* xrow = xp + r * (HH / 4);
            #pragma unroll 8
            for (int q = 0; q < HH / 4; ++q) {
                float4 xv = xrow[q];         // broadcast LDG.128
                float4 o;
                OUT_STEP(xv.x, o.x); OUT_STEP(xv.y, o.y);
                OUT_STEP(xv.z, o.z); OUT_STEP(xv.w, o.w);
                *(float4*)&rw[q * 4] = o;    // conflict-free STS.128
            }
            __syncthreads();                 // row r staged
        }
    } else {
        // ---------------- flusher: transpose + spikes --------------------
        const int lane = tid - 32;
        float* __restrict__ outp = outbuf;
        float* __restrict__ spkp = outbuf + BSNH;

        for (int r = 0; r < BLKROWS; ++r) {
            __syncthreads();                 // wait for row r
            const float* buf = sbuf[r & 1];
            const int s = s0 + r;
            size_t base = (((size_t)b * SS + s) * NN + n0) * HH + lane * 4;
            #pragma unroll 4
            for (int rr = 0; rr < 32; ++rr) {
                float4 vv = *(const float4*)&buf[rr * ROWPAD + lane * 4];
                *(float4*)&outp[base + (size_t)rr * HH] = vv;  // 512B coalesced
                if (write_spikes) {
                    float4 sp;
                    sp.x = (vv.x > 0.0f) ? 1.0f : 0.0f;
                    sp.y = (vv.y > 0.0f) ? 1.0f : 0.0f;
                    sp.z = (vv.z > 0.0f) ? 1.0f : 0.0f;
                    sp.w = (vv.w > 0.0f) ? 1.0f : 0.0f;
                    *(float4*)&spkp[base + (size_t)rr * HH] = sp;
                }
            }
        }
    }
}

extern "C" void kernel_launch(void* const* d_in, const int* in_sizes, int n_in,
                              void* d_out, int out_size)
{
    const float* x      = (const float*)d_in[0];  // [16, 256, 128] f32
    const float* thresh = (const float*)d_in[1];  // [64] f32
    const float* acc0   = (const float*)d_in[2];  // [16, 64] f32
    float* out = (float*)d_out;

    int write_spikes = ((size_t)out_size >= 2 * BSNH) ? 1 : 0;

    lif_prepass<<<BB * 2, 64>>>(x, thresh, acc0);
    lif_output<<<BB * 2 * NBLK, 64>>>(x, thresh, out, write_spikes);
}